// round 14
// baseline (speedup 1.0000x reference)
#include <cuda_runtime.h>
#include <cuda_bf16.h>
#include <cstdint>
#include <math.h>

// Problem constants: B=8, N=512, H=W=64 -> M=4096
#define BB     8
#define MPIX   4096
#define NMAT   16
#define MATSZ  (512*512)
#define TPAD   132

// ---------------- device scratch ----------------
__device__ float g_cov [NMAT * MATSZ];
__device__ float g_part[128  * MATSZ];          // gram partials: 8 K-splits x 16 mats
__device__ float g_inv [8    * MATSZ];          // zero-init; strict-upper blocks stay 0
__device__ float g_T   [8    * MATSZ];
__device__ float g_mean[NMAT * 512];
__device__ float g_msum[NMAT * 512 * 4];
__device__ float g_bias[8    * 512];
__device__ float g_dinv[NMAT * 8 * 64 * 64];    // per-step inv of 64x64 diag blocks

__device__ __nv_bfloat16 g_xhi[NMAT * 512 * 4096];
__device__ __nv_bfloat16 g_xlo[NMAT * 512 * 4096];
__device__ __nv_bfloat16 g_thi[8 * MATSZ];      // zero-init; strict-upper tiles stay 0
__device__ __nv_bfloat16 g_tlo[8 * MATSZ];

// ============================ asm helpers ============================
__device__ __forceinline__ uint32_t smem_to_u32(const void* p) {
    uint32_t a;
    asm("{ .reg .u64 t; cvta.to.shared.u64 t, %1; cvt.u32.u64 %0, t; }" : "=r"(a) : "l"(p));
    return a;
}
__device__ __forceinline__ void ldsm_x4(uint32_t* r, uint32_t addr) {
    asm volatile("ldmatrix.sync.aligned.m8n8.x4.shared.b16 {%0,%1,%2,%3}, [%4];"
        : "=r"(r[0]), "=r"(r[1]), "=r"(r[2]), "=r"(r[3]) : "r"(addr));
}
__device__ __forceinline__ void ldsm_x2(uint32_t* r, uint32_t addr) {
    asm volatile("ldmatrix.sync.aligned.m8n8.x2.shared.b16 {%0,%1}, [%2];"
        : "=r"(r[0]), "=r"(r[1]) : "r"(addr));
}
__device__ __forceinline__ void ldsm_x4_trans(uint32_t* r, uint32_t addr) {
    asm volatile("ldmatrix.sync.aligned.m8n8.x4.trans.shared.b16 {%0,%1,%2,%3}, [%4];"
        : "=r"(r[0]), "=r"(r[1]), "=r"(r[2]), "=r"(r[3]) : "r"(addr));
}
__device__ __forceinline__ void mma16816(float* d, const uint32_t* a, const uint32_t* b) {
    asm volatile("mma.sync.aligned.m16n8k16.row.col.f32.bf16.bf16.f32 "
        "{%0,%1,%2,%3}, {%4,%5,%6,%7}, {%8,%9}, {%0,%1,%2,%3};"
        : "+f"(d[0]), "+f"(d[1]), "+f"(d[2]), "+f"(d[3])
        : "r"(a[0]), "r"(a[1]), "r"(a[2]), "r"(a[3]), "r"(b[0]), "r"(b[1]));
}
#define CP_ASYNC16(sa, gp) \
    asm volatile("cp.async.cg.shared.global [%0], [%1], 16;" :: "r"(sa), "l"(gp))
#define CP_COMMIT() asm volatile("cp.async.commit_group;" ::: "memory")
#define CP_WAIT(n)  asm volatile("cp.async.wait_group %0;" :: "n"(n) : "memory")

// ---------------- 1) fp32 -> bf16 hi/lo split + fused mean partials ----------------
__global__ void convert_x(const float* __restrict__ cont, const float* __restrict__ styl) {
    const size_t i4 = (size_t)blockIdx.x * 256 + threadIdx.x;
    const float4 v = (i4 < 4194304) ? ((const float4*)cont)[i4]
                                    : ((const float4*)styl)[i4 - 4194304];
    float x[4] = {v.x, v.y, v.z, v.w};
    unsigned short hs[4], ls[4];
    #pragma unroll
    for (int j = 0; j < 4; ++j) {
        __nv_bfloat16 h = __float2bfloat16_rn(x[j]);
        __nv_bfloat16 l = __float2bfloat16_rn(x[j] - __bfloat162float(h));
        hs[j] = __bfloat16_as_ushort(h);
        ls[j] = __bfloat16_as_ushort(l);
    }
    ((uint2*)g_xhi)[i4] = make_uint2((uint32_t)hs[0] | ((uint32_t)hs[1] << 16),
                                     (uint32_t)hs[2] | ((uint32_t)hs[3] << 16));
    ((uint2*)g_xlo)[i4] = make_uint2((uint32_t)ls[0] | ((uint32_t)ls[1] << 16),
                                     (uint32_t)ls[2] | ((uint32_t)ls[3] << 16));
    float s = x[0] + x[1] + x[2] + x[3];
    __shared__ float red[256];
    red[threadIdx.x] = s;
    __syncthreads();
    for (int o = 128; o >= 32; o >>= 1) {
        if (threadIdx.x < o) red[threadIdx.x] += red[threadIdx.x + o];
        __syncthreads();
    }
    if (threadIdx.x < 32) {
        float w = red[threadIdx.x];
        #pragma unroll
        for (int o = 16; o; o >>= 1) w += __shfl_xor_sync(0xffffffffu, w, o);
        if (threadIdx.x == 0) g_msum[blockIdx.x] = w;
    }
}

__global__ void finalize_mean() {
    const int idx = blockIdx.x * 256 + threadIdx.x;
    g_mean[idx] = (g_msum[4 * idx] + g_msum[4 * idx + 1] +
                   g_msum[4 * idx + 2] + g_msum[4 * idx + 3]) * (1.f / (float)MPIX);
}

// ---------------- 2) gram GEMM (K-split=8, 3-stage pipeline) ----------------
#define KC       64
#define RSTRIDE  144
#define OPBYTES  (128 * RSTRIDE)
#define RSTRIDEB 272
#define OPBYTESB (64 * RSTRIDEB)
#define STAGEB   (4 * OPBYTES)          // 73728
#define SMEMB    (3 * STAGEB)           // 221184

__global__ void __launch_bounds__(512, 1) gram_gemm() {
    const int p = blockIdx.x;
    int bi = 0;
    while ((bi + 1) * (bi + 2) / 2 <= p) ++bi;
    const int bj = p - bi * (bi + 1) / 2;
    const bool diag = (bi == bj);
    const int mat = blockIdx.z & 15;
    const int split = blockIdx.z >> 4;          // 0..7
    const size_t base = (size_t)mat * 512 * 4096;
    const int K = 4096, NT = 8;
    const int koff = split * 512;
    const __nv_bfloat16* Ah = g_xhi + base + koff + (size_t)(bi * 128) * K;
    const __nv_bfloat16* Al = g_xlo + base + koff + (size_t)(bi * 128) * K;
    const __nv_bfloat16* Bh = g_xhi + base + koff + (size_t)(bj * 128) * K;
    const __nv_bfloat16* Bl = g_xlo + base + koff + (size_t)(bj * 128) * K;

    extern __shared__ __align__(128) char smem[];
    const uint32_t sb = smem_to_u32(smem);
    const int t = threadIdx.x, wid = t >> 5, lane = t & 31;
    const int wm = wid & 3, wn = wid >> 2;
    const int r0 = t >> 3, seg = t & 7;

    float acc[2][4][4];
    #pragma unroll
    for (int a = 0; a < 2; ++a)
        #pragma unroll
        for (int b = 0; b < 4; ++b)
            #pragma unroll
            for (int c = 0; c < 4; ++c) acc[a][b][c] = 0.f;

    const __nv_bfloat16* srcs[4] = {Ah, Al, Bh, Bl};

    auto load_chunk = [&](int c, int stage) {
        const uint32_t s0 = sb + stage * STAGEB;
        #pragma unroll
        for (int op = 0; op < 4; ++op) {
            const __nv_bfloat16* src = srcs[op] + (size_t)c * KC;
            const uint32_t sop = s0 + op * OPBYTES;
            #pragma unroll
            for (int i = 0; i < 2; ++i) {
                const int row = r0 + 64 * i;
                CP_ASYNC16(sop + row * RSTRIDE + seg * 16,
                           src + (size_t)row * K + seg * 8);
            }
        }
    };

    const int l15 = lane & 15;
    const uint32_t a_lane_off = (uint32_t)((wm * 32 + l15) * RSTRIDE + (lane >> 4) * 16);
    const uint32_t b_lane_off = (uint32_t)(2 * OPBYTES +
                                (wn * 32 + (l15 & 7)) * RSTRIDE + ((l15 >> 3) & 1) * 16);

    load_chunk(0, 0); CP_COMMIT();
    load_chunk(1, 1); CP_COMMIT();

    for (int c = 0; c < NT; ++c) {
        const int st = c % 3;
        if (c + 2 < NT) { load_chunk(c + 2, (c + 2) % 3); CP_COMMIT(); CP_WAIT(2); }
        else if (c + 1 < NT) { CP_WAIT(1); }
        else { CP_WAIT(0); }
        __syncthreads();

        const uint32_t base2 = sb + st * STAGEB;
        #pragma unroll
        for (int ks = 0; ks < 4; ++ks) {
            uint32_t ah[2][4], al[2][4], bh[4][2], bl[4][2];
            #pragma unroll
            for (int mt = 0; mt < 2; ++mt) {
                const uint32_t aaddr = base2 + a_lane_off + mt * (16 * RSTRIDE) + ks * 32;
                ldsm_x4(ah[mt], aaddr);
                ldsm_x4(al[mt], aaddr + OPBYTES);
            }
            #pragma unroll
            for (int nt = 0; nt < 4; ++nt) {
                const uint32_t baddr = base2 + b_lane_off + nt * (8 * RSTRIDE) + ks * 32;
                ldsm_x2(bh[nt], baddr);
                ldsm_x2(bl[nt], baddr + OPBYTES);
            }
            #pragma unroll
            for (int mt = 0; mt < 2; ++mt)
                #pragma unroll
                for (int nt = 0; nt < 4; ++nt) {
                    mma16816(acc[mt][nt], ah[mt], bh[nt]);
                    mma16816(acc[mt][nt], ah[mt], bl[nt]);
                    mma16816(acc[mt][nt], al[mt], bh[nt]);
                }
        }
        __syncthreads();
    }

    const int qr = lane >> 2, qc = (lane & 3) * 2;
    float* P = g_part + (size_t)((split << 4) + mat) * MATSZ;
    #pragma unroll
    for (int mt = 0; mt < 2; ++mt)
        #pragma unroll
        for (int v = 0; v < 2; ++v) {
            const int gr = bi * 128 + wm * 32 + mt * 16 + qr + v * 8;
            #pragma unroll
            for (int nt = 0; nt < 4; ++nt)
                #pragma unroll
                for (int j = 0; j < 2; ++j) {
                    const int gc = bj * 128 + wn * 32 + nt * 8 + qc + j;
                    if (!diag || gc <= gr)
                        P[(size_t)gr * 512 + gc] = acc[mt][nt][v * 2 + j];
                }
        }
}

// ---------------- 3) out GEMM: out = T @ xc + bias (trans-B, 3-stage) ----------------
__global__ void __launch_bounds__(512, 1) out_gemm(float* __restrict__ outp) {
    const int bi = blockIdx.x, bj = blockIdx.y, mat = blockIdx.z;
    const int NT = (bi + 1) * 2;
    const __nv_bfloat16* Ah = g_thi + (size_t)mat * MATSZ + (size_t)(bi * 128) * 512;
    const __nv_bfloat16* Al = g_tlo + (size_t)mat * MATSZ + (size_t)(bi * 128) * 512;
    const __nv_bfloat16* Bh = g_xhi + (size_t)mat * 512 * 4096 + bj * 128;
    const __nv_bfloat16* Bl = g_xlo + (size_t)mat * 512 * 4096 + bj * 128;

    extern __shared__ __align__(128) char smem[];
    const uint32_t sb = smem_to_u32(smem);
    const int t = threadIdx.x, wid = t >> 5, lane = t & 31;
    const int wm = wid & 3, wn = wid >> 2;
    const int r0 = t >> 3, seg = t & 7;

    float acc[2][4][4];
    #pragma unroll
    for (int a = 0; a < 2; ++a)
        #pragma unroll
        for (int b = 0; b < 4; ++b)
            #pragma unroll
            for (int c = 0; c < 4; ++c) acc[a][b][c] = 0.f;

    auto load_chunk = [&](int c, int stage) {
        const uint32_t s0 = sb + stage * STAGEB;
        #pragma unroll
        for (int i = 0; i < 2; ++i) {
            const int row = r0 + 64 * i;
            const size_t go = (size_t)row * 512 + (size_t)c * KC + seg * 8;
            CP_ASYNC16(s0 + row * RSTRIDE + seg * 16, Ah + go);
            CP_ASYNC16(s0 + OPBYTES + row * RSTRIDE + seg * 16, Al + go);
        }
        #pragma unroll
        for (int i = 0; i < 2; ++i) {
            const int s = seg + 8 * i;
            const size_t go = (size_t)(c * KC + r0) * 4096 + s * 8;
            CP_ASYNC16(s0 + 2 * OPBYTES + r0 * RSTRIDEB + s * 16, Bh + go);
            CP_ASYNC16(s0 + 2 * OPBYTES + OPBYTESB + r0 * RSTRIDEB + s * 16, Bl + go);
        }
    };

    const int l15 = lane & 15;
    const uint32_t a_lane_off = (uint32_t)((wm * 32 + l15) * RSTRIDE + (lane >> 4) * 16);
    const uint32_t b_lane_off = (uint32_t)(2 * OPBYTES + (lane & 15) * RSTRIDEB +
                                           (wn * 32 + ((lane >> 4) & 1) * 8) * 2);

    load_chunk(0, 0); CP_COMMIT();
    load_chunk(1, 1); CP_COMMIT();

    for (int c = 0; c < NT; ++c) {
        const int st = c % 3;
        if (c + 2 < NT) { load_chunk(c + 2, (c + 2) % 3); CP_COMMIT(); CP_WAIT(2); }
        else if (c + 1 < NT) { CP_WAIT(1); }
        else { CP_WAIT(0); }
        __syncthreads();

        const uint32_t base2 = sb + st * STAGEB;
        #pragma unroll
        for (int ks = 0; ks < 4; ++ks) {
            uint32_t ah[2][4], al[2][4], bh[4][2], bl[4][2];
            #pragma unroll
            for (int mt = 0; mt < 2; ++mt) {
                const uint32_t aaddr = base2 + a_lane_off + mt * (16 * RSTRIDE) + ks * 32;
                ldsm_x4(ah[mt], aaddr);
                ldsm_x4(al[mt], aaddr + OPBYTES);
            }
            #pragma unroll
            for (int ntp = 0; ntp < 2; ++ntp) {
                const uint32_t baddr = base2 + b_lane_off + ks * (16 * RSTRIDEB) + ntp * 32;
                uint32_t r4[4];
                ldsm_x4_trans(r4, baddr);
                bh[2 * ntp][0] = r4[0]; bh[2 * ntp][1] = r4[1];
                bh[2 * ntp + 1][0] = r4[2]; bh[2 * ntp + 1][1] = r4[3];
                ldsm_x4_trans(r4, baddr + OPBYTESB);
                bl[2 * ntp][0] = r4[0]; bl[2 * ntp][1] = r4[1];
                bl[2 * ntp + 1][0] = r4[2]; bl[2 * ntp + 1][1] = r4[3];
            }
            #pragma unroll
            for (int mt = 0; mt < 2; ++mt)
                #pragma unroll
                for (int nt = 0; nt < 4; ++nt) {
                    mma16816(acc[mt][nt], ah[mt], bh[nt]);
                    mma16816(acc[mt][nt], ah[mt], bl[nt]);
                    mma16816(acc[mt][nt], al[mt], bh[nt]);
                }
        }
        __syncthreads();
    }

    const int qr = lane >> 2, qc = (lane & 3) * 2;
    #pragma unroll
    for (int mt = 0; mt < 2; ++mt)
        #pragma unroll
        for (int v = 0; v < 2; ++v) {
            const int gm = bi * 128 + wm * 32 + mt * 16 + qr + v * 8;
            const float bv = g_bias[mat * 512 + gm];
            float* orow = outp + ((size_t)mat * 512 + gm) * 4096 + bj * 128 + wn * 32;
            #pragma unroll
            for (int nt = 0; nt < 4; ++nt) {
                float2 pr;
                pr.x = acc[mt][nt][v * 2 + 0] + bv;
                pr.y = acc[mt][nt][v * 2 + 1] + bv;
                *(float2*)&orow[nt * 8 + qc] = pr;
            }
        }
}

// combine 8 partials; mirror = 0 (upper never read downstream)
__global__ void combine_cov() {
    const int mat = blockIdx.y, i = blockIdx.x;
    const float* mrow = g_mean + mat * 512;
    float* C = g_cov + (size_t)mat * MATSZ;
    const float mi = mrow[i] * (float)MPIX;
    const float invm1 = 1.f / (float)(MPIX - 1);
    for (int j = threadIdx.x; j <= i; j += 256) {
        const size_t o = (size_t)i * 512 + j;
        float s = 0.f;
        #pragma unroll
        for (int sp = 0; sp < 8; ++sp)
            s += g_part[(size_t)((sp << 4) + mat) * MATSZ + o];
        C[o] = (s - mi * mrow[j]) * invm1;
        if (j < i) C[(size_t)j * 512 + i] = 0.f;
    }
}

// ---------------- 4) blocked Cholesky (bs=64), 256 threads, micro-blocked ----------
__global__ void __launch_bounds__(256) chol_diag(int s) {
    const int mat = blockIdx.x;
    float* A = g_cov + (size_t)mat * MATSZ;
    __shared__ float sA[64][65];
    __shared__ float sW[64][65];
    const int t = threadIdx.x;
    for (int idx = t; idx < 4096; idx += 256) {
        int r = idx >> 6, c = idx & 63;
        sA[r][c] = A[(size_t)(s * 64 + r) * 512 + s * 64 + c];
        sW[r][c] = 0.f;
    }
    __syncthreads();

    for (int sbk = 0; sbk < 8; ++sbk) {
        const int o = sbk * 8;
        if (t < 8) {
            const int r = t;
            for (int j = 0; j < 8; ++j) {
                if (r == j) sA[o + j][o + j] = sqrtf(sA[o + j][o + j]);
                __syncwarp(0xFFu);
                const float d = sA[o + j][o + j];
                if (r > j) sA[o + r][o + j] /= d;
                __syncwarp(0xFFu);
                if (r > j) {
                    const float lrj = sA[o + r][o + j];
                    for (int c = j + 1; c <= r; ++c) sA[o + r][o + c] -= lrj * sA[o + c][o + j];
                }
                __syncwarp(0xFFu);
            }
        }
        __syncthreads();
        const int nrem = 64 - o - 8;
        if (nrem > 0) {
            if (t < nrem) {
                const int r = o + 8 + t;
                float x[8];
                #pragma unroll
                for (int j = 0; j < 8; ++j) {
                    float v = sA[r][o + j];
                    #pragma unroll
                    for (int k = 0; k < 8; ++k)
                        if (k < j) v -= x[k] * sA[o + j][o + k];
                    x[j] = v / sA[o + j][o + j];
                }
                #pragma unroll
                for (int j = 0; j < 8; ++j) sA[r][o + j] = x[j];
            }
            __syncthreads();
            const int tot = nrem * nrem;
            for (int e = t; e < tot; e += 256) {
                const int r = o + 8 + e / nrem, c = o + 8 + e % nrem;
                float v = sA[r][c];
                #pragma unroll
                for (int k = 0; k < 8; ++k) v -= sA[r][o + k] * sA[c][o + k];
                sA[r][c] = v;
            }
            __syncthreads();
        }
    }

    {
        const int col = t >> 2, part = t & 3;
        const uint32_t qmask = 0xFu << ((t & 31) & ~3u);
        if (part == 0) sW[col][col] = 1.f / sA[col][col];
        __syncwarp(qmask);
        for (int i = col + 1; i < 64; ++i) {
            float psum = 0.f;
            for (int k = col + part; k < i; k += 4) psum += sA[i][k] * sW[k][col];
            psum += __shfl_down_sync(qmask, psum, 1);
            psum += __shfl_down_sync(qmask, psum, 2);
            if (part == 0) sW[i][col] = -psum / sA[i][i];
            __syncwarp(qmask);
        }
    }
    __syncthreads();

    float* D = g_dinv + (size_t)(mat * 8 + s) * 4096;
    float* W = (mat < 8) ? (g_inv + (size_t)mat * MATSZ) : nullptr;
    for (int idx = t; idx < 4096; idx += 256) {
        int r = idx >> 6, c = idx & 63;
        if (c <= r) A[(size_t)(s * 64 + r) * 512 + s * 64 + c] = sA[r][c];
        D[idx] = sW[r][c];
        if (W) W[(size_t)(s * 64 + r) * 512 + s * 64 + c] = sW[r][c];
    }
}

// TRSM as GEMM: panel = A21 * invL11^T
__global__ void __launch_bounds__(256) trsm_gemm(int s) {
    const int mat = blockIdx.y;
    float* A = g_cov + (size_t)mat * MATSZ;
    const float* D = g_dinv + (size_t)(mat * 8 + s) * 4096;
    const int g0 = (s + 1) * 64 + blockIdx.x * 64;
    __shared__ float sa[64][68];
    __shared__ float sw[64][68];
    const int t = threadIdx.x;
    {
        const int row = t >> 2, kq = t & 3;
        #pragma unroll
        for (int i2 = 0; i2 < 4; ++i2) {
            const int k = kq * 16 + i2 * 4;
            float4 va = *(const float4*)&A[(size_t)(g0 + row) * 512 + s * 64 + k];
            sa[k + 0][row] = va.x; sa[k + 1][row] = va.y; sa[k + 2][row] = va.z; sa[k + 3][row] = va.w;
            float4 vw = *(const float4*)&D[row * 64 + k];
            sw[k + 0][row] = vw.x; sw[k + 1][row] = vw.y; sw[k + 2][row] = vw.z; sw[k + 3][row] = vw.w;
        }
    }
    __syncthreads();
    const int i0 = (t >> 4) << 2, j0 = (t & 15) << 2;
    float acc[4][4];
    #pragma unroll
    for (int i = 0; i < 4; ++i)
        #pragma unroll
        for (int j = 0; j < 4; ++j) acc[i][j] = 0.f;
    #pragma unroll 8
    for (int k = 0; k < 64; ++k) {
        float4 a = *(const float4*)&sa[k][i0];
        float4 b = *(const float4*)&sw[k][j0];
        float av[4] = {a.x, a.y, a.z, a.w}, bv[4] = {b.x, b.y, b.z, b.w};
        #pragma unroll
        for (int i = 0; i < 4; ++i)
            #pragma unroll
            for (int j = 0; j < 4; ++j) acc[i][j] += av[i] * bv[j];
    }
    #pragma unroll
    for (int i = 0; i < 4; ++i)
        #pragma unroll
        for (int j = 0; j < 4; ++j)
            A[(size_t)(g0 + i0 + i) * 512 + s * 64 + j0 + j] = acc[i][j];
}

__global__ void __launch_bounds__(256) syrk_update(int s) {
    const int ti = blockIdx.x, tj = blockIdx.y, mat = blockIdx.z;
    if (ti < tj) return;
    float* A = g_cov + (size_t)mat * MATSZ;
    const int base = (s + 1) * 64;
    const int R0 = base + ti * 64, C0 = base + tj * 64;
    __shared__ float sa[64][68];
    __shared__ float sb2[64][68];
    const int t = threadIdx.x;
    {
        const int row = t >> 2, kq = t & 3;
        #pragma unroll
        for (int i2 = 0; i2 < 4; ++i2) {
            const int k = kq * 16 + i2 * 4;
            float4 va = *(const float4*)&A[(size_t)(R0 + row) * 512 + s * 64 + k];
            sa[k + 0][row] = va.x; sa[k + 1][row] = va.y; sa[k + 2][row] = va.z; sa[k + 3][row] = va.w;
            float4 vb = *(const float4*)&A[(size_t)(C0 + row) * 512 + s * 64 + k];
            sb2[k + 0][row] = vb.x; sb2[k + 1][row] = vb.y; sb2[k + 2][row] = vb.z; sb2[k + 3][row] = vb.w;
        }
    }
    __syncthreads();
    const int i0 = (t >> 4) << 2, j0 = (t & 15) << 2;
    float acc[4][4];
    #pragma unroll
    for (int i = 0; i < 4; ++i)
        #pragma unroll
        for (int j = 0; j < 4; ++j) acc[i][j] = 0.f;
    #pragma unroll 8
    for (int k = 0; k < 64; ++k) {
        float4 a = *(const float4*)&sa[k][i0];
        float4 b = *(const float4*)&sb2[k][j0];
        float av[4] = {a.x, a.y, a.z, a.w}, bv[4] = {b.x, b.y, b.z, b.w};
        #pragma unroll
        for (int i = 0; i < 4; ++i)
            #pragma unroll
            for (int j = 0; j < 4; ++j) acc[i][j] += av[i] * bv[j];
    }
    #pragma unroll
    for (int i = 0; i < 4; ++i) {
        const int li = i0 + i;
        #pragma unroll
        for (int j = 0; j < 4; ++j) {
            const int lj = j0 + j;
            if (ti != tj || li >= lj)
                A[(size_t)(R0 + li) * 512 + C0 + lj] -= acc[i][j];
        }
    }
}

// ---------------- 5) blocked inv(Lc): fused column-sweep (512 threads) ----------------
#define SWELEM 4160
#define TRINV_SMEM ((8 * SWELEM + 2 * 64 * 68) * 4)

__global__ void __launch_bounds__(512) trinv_cols() {
    const int jb = blockIdx.x % 7, mat = blockIdx.x / 7;
    const float* L = g_cov + (size_t)mat * MATSZ;
    float* W = g_inv + (size_t)mat * MATSZ;

    extern __shared__ float sm[];
    float* sW = sm;
    float* sa = sm + 8 * SWELEM;
    float* sb = sa + 64 * 68;
    #define SWB(b, r, c) sW[(b) * SWELEM + (r) * 65 + (c)]
    #define SAB(r, c)    sa[(r) * 68 + (c)]
    #define SBB(r, c)    sb[(r) * 68 + (c)]

    const int t = threadIdx.x;
    const int i0 = (t >> 4) << 1, j0 = (t & 15) << 2;   // 2x4 micro-tile, 512 threads

    for (int idx = t; idx < 4096; idx += 512) {
        int r = idx >> 6, c = idx & 63;
        SWB(0, r, c) = W[(size_t)(jb * 64 + r) * 512 + jb * 64 + c];
    }
    __syncthreads();

    for (int ib = jb + 1; ib < 8; ++ib) {
        float acc[2][4];
        #pragma unroll
        for (int i = 0; i < 2; ++i)
            #pragma unroll
            for (int j = 0; j < 4; ++j) acc[i][j] = 0.f;

        for (int k = jb; k < ib; ++k) {
            __syncthreads();
            {
                const int row = t >> 3, kq = t & 7;
                #pragma unroll
                for (int i2 = 0; i2 < 2; ++i2) {
                    const int kk = kq * 8 + i2 * 4;
                    float4 va = *(const float4*)&L[(size_t)(ib * 64 + row) * 512 + k * 64 + kk];
                    SAB(kk + 0, row) = va.x; SAB(kk + 1, row) = va.y;
                    SAB(kk + 2, row) = va.z; SAB(kk + 3, row) = va.w;
                }
            }
            __syncthreads();
            const int kb = k - jb;
            #pragma unroll 8
            for (int kk = 0; kk < 64; ++kk) {
                float av[2], bv[4];
                #pragma unroll
                for (int i = 0; i < 2; ++i) av[i] = SAB(kk, i0 + i);
                #pragma unroll
                for (int j = 0; j < 4; ++j) bv[j] = SWB(kb, kk, j0 + j);
                #pragma unroll
                for (int i = 0; i < 2; ++i)
                    #pragma unroll
                    for (int j = 0; j < 4; ++j) acc[i][j] += av[i] * bv[j];
            }
        }
        __syncthreads();
        #pragma unroll
        for (int i = 0; i < 2; ++i)
            #pragma unroll
            for (int j = 0; j < 4; ++j) SBB(i0 + i, j0 + j) = acc[i][j];
        {
            const int row = t >> 3, kq = t & 7;
            #pragma unroll
            for (int i2 = 0; i2 < 2; ++i2) {
                const int kk = kq * 8 + i2 * 4;
                float4 va = *(const float4*)&W[(size_t)(ib * 64 + row) * 512 + ib * 64 + kk];
                SAB(kk + 0, row) = va.x; SAB(kk + 1, row) = va.y;
                SAB(kk + 2, row) = va.z; SAB(kk + 3, row) = va.w;
            }
        }
        __syncthreads();
        float acc2[2][4];
        #pragma unroll
        for (int i = 0; i < 2; ++i)
            #pragma unroll
            for (int j = 0; j < 4; ++j) acc2[i][j] = 0.f;
        #pragma unroll 8
        for (int kk = 0; kk < 64; ++kk) {
            float av[2], bv[4];
            #pragma unroll
            for (int i = 0; i < 2; ++i) av[i] = SAB(kk, i0 + i);
            #pragma unroll
            for (int j = 0; j < 4; ++j) bv[j] = SBB(kk, j0 + j);
            #pragma unroll
            for (int i = 0; i < 2; ++i)
                #pragma unroll
                for (int j = 0; j < 4; ++j) acc2[i][j] += av[i] * bv[j];
        }
        const int kb = ib - jb;
        #pragma unroll
        for (int i = 0; i < 2; ++i)
            #pragma unroll
            for (int j = 0; j < 4; ++j) {
                const float v = -acc2[i][j];
                SWB(kb, i0 + i, j0 + j) = v;
                W[(size_t)(ib * 64 + i0 + i) * 512 + jb * 64 + j0 + j] = v;
            }
    }
}

// ---------------- 6) triangular T = Ls @ W; fused bf16 split epilogue ----------------
__global__ void __launch_bounds__(256) gemm_nn_tri() {
    const int p = blockIdx.x, mat = blockIdx.y;
    int bm = 0;
    while ((bm + 1) * (bm + 2) / 2 <= p) ++bm;
    const int bn = p - bm * (bm + 1) / 2;
    const float* A = g_cov + (size_t)(8 + mat) * MATSZ;
    const float* B = g_inv + (size_t)mat * MATSZ;
    float* C = g_T + (size_t)mat * MATSZ;

    __shared__ float As[2][16][TPAD];
    __shared__ float Bs[2][16][128];

    const int t = threadIdx.x;
    const int arow = t & 127, akg = t >> 7;
    const int kt0 = bn * 8;
    const int NT = (bm + 1) * 8 - kt0;
    const float* aptr = A + (size_t)(bm * 128 + arow) * 512 + kt0 * 16 + akg * 8;
    const int bkr = t >> 5, bc = (t & 31) << 2;
    const float* bptr = B + (size_t)(kt0 * 16 + bkr) * 512 + bn * 128 + bc;
    const int m0 = (t >> 4) << 3, n0 = (t & 15) << 3;

    float acc[8][8];
    #pragma unroll
    for (int i = 0; i < 8; ++i)
        #pragma unroll
        for (int j = 0; j < 8; ++j) acc[i][j] = 0.f;

    {
        float av[8];
        *(float4*)&av[0] = *(const float4*)(aptr);
        *(float4*)&av[4] = *(const float4*)(aptr + 4);
        const int kb = akg * 8;
        #pragma unroll
        for (int c = 0; c < 8; ++c) As[0][kb + c][arow] = av[c];
        float4 v0 = *(const float4*)(bptr);
        float4 v1 = *(const float4*)(bptr + (size_t)8 * 512);
        *(float4*)&Bs[0][bkr][bc]     = v0;
        *(float4*)&Bs[0][bkr + 8][bc] = v1;
    }
    __syncthreads();

    for (int kt = 0; kt < NT; ++kt) {
        const int cur = kt & 1;
        if (kt + 1 < NT) {
            const int nb = cur ^ 1;
            float av[8];
            const float* ap = aptr + (kt + 1) * 16;
            *(float4*)&av[0] = *(const float4*)(ap);
            *(float4*)&av[4] = *(const float4*)(ap + 4);
            const int kb = akg * 8;
            #pragma unroll
            for (int c = 0; c < 8; ++c) As[nb][kb + c][arow] = av[c];
            const float* bp = bptr + (size_t)((kt + 1) * 16) * 512;
            float4 v0 = *(const float4*)(bp);
            float4 v1 = *(const float4*)(bp + (size_t)8 * 512);
            *(float4*)&Bs[nb][bkr][bc]     = v0;
            *(float4*)&Bs[nb][bkr + 8][bc] = v1;
        }
        #pragma unroll
        for (int k = 0; k < 16; ++k) {
            float a[8], b[8];
            *(float4*)&a[0] = *(const float4*)&As[cur][k][m0];
            *(float4*)&a[4] = *(const float4*)&As[cur][k][m0 + 4];
            *(float4*)&b[0] = *(const float4*)&Bs[cur][k][n0];
            *(float4*)&b[4] = *(const float4*)&Bs[cur][k][n0 + 4];
            #pragma unroll
            for (int i = 0; i < 8; ++i)
                #pragma unroll
                for (int j = 0; j < 8; ++j) acc[i][j] += a[i] * b[j];
        }
        __syncthreads();
    }

    const bool dtile = (bm == bn);
    __nv_bfloat16* TH = g_thi + (size_t)mat * MATSZ;
    __nv_bfloat16* TL = g_tlo + (size_t)mat * MATSZ;
    #pragma unroll
    for (int i = 0; i < 8; ++i) {
        const int gi = bm * 128 + m0 + i;
        #pragma unroll
        for (int j = 0; j < 8; ++j) {
            const int gj = bn * 128 + n0 + j;
            const float v = acc[i][j];
            C[(size_t)gi * 512 + gj] = v;
            const float vm = (dtile && gj > gi) ? 0.f : v;
            __nv_bfloat16 h = __float2bfloat16_rn(vm);
            __nv_bfloat16 l = __float2bfloat16_rn(vm - __bfloat162float(h));
            TH[(size_t)gi * 512 + gj] = h;
            TL[(size_t)gi * 512 + gj] = l;
        }
    }
}

// ---------------- 7) bias = ms - T @ mc ----------------
__global__ void bias_kernel() {
    const int w = threadIdx.x >> 5, lane = threadIdx.x & 31;
    const int g = blockIdx.x * 8 + w;
    const int b = g >> 9, i = g & 511;
    const float* Trow = g_T + (size_t)b * MATSZ + (size_t)i * 512;
    const float* mc = g_mean + b * 512;
    float acc = 0.f;
    for (int k = lane; k <= i; k += 32) acc += Trow[k] * mc[k];
    #pragma unroll
    for (int o = 16; o; o >>= 1) acc += __shfl_xor_sync(0xffffffffu, acc, o);
    if (lane == 0) g_bias[g] = g_mean[(8 + b) * 512 + i] - acc;
}

// ---------------- launcher ----------------
extern "C" void kernel_launch(void* const* d_in, const int* in_sizes, int n_in,
                              void* d_out, int out_size) {
    const float* cont = (const float*)d_in[0];
    const float* styl = (const float*)d_in[1];
    float* out = (float*)d_out;

    cudaFuncSetAttribute(gram_gemm, cudaFuncAttributeMaxDynamicSharedMemorySize, SMEMB);
    cudaFuncSetAttribute(out_gemm,  cudaFuncAttributeMaxDynamicSharedMemorySize, SMEMB);
    cudaFuncSetAttribute(trinv_cols, cudaFuncAttributeMaxDynamicSharedMemorySize, TRINV_SMEM);

    convert_x<<<32768, 256>>>(cont, styl);
    finalize_mean<<<32, 256>>>();

    gram_gemm<<<dim3(10, 1, 128), 512, SMEMB>>>();
    combine_cov<<<dim3(512, 16), 256>>>();

    for (int s = 0; s < 8; ++s) {
        chol_diag<<<NMAT, 256>>>(s);
        const int nrem = 512 - (s + 1) * 64;
        if (nrem > 0) {
            trsm_gemm<<<dim3(nrem / 64, NMAT), 256>>>(s);
            syrk_update<<<dim3(nrem / 64, nrem / 64, NMAT), 256>>>(s);
        }
    }

    trinv_cols<<<56, 512, TRINV_SMEM>>>();

    gemm_nn_tri<<<dim3(10, 8), 256>>>();

    bias_kernel<<<512, 256>>>();
    out_gemm<<<dim3(4, 32, 8), 512, SMEMB>>>(out);
}

// round 15
// speedup vs baseline: 1.0395x; 1.0395x over previous
#include <cuda_runtime.h>
#include <cuda_bf16.h>
#include <cstdint>
#include <math.h>

// Problem constants: B=8, N=512, H=W=64 -> M=4096
#define BB     8
#define MPIX   4096
#define NMAT   16
#define MATSZ  (512*512)
#define TPAD   132

// ---------------- device scratch ----------------
__device__ float g_cov [NMAT * MATSZ];
__device__ float g_part[128  * MATSZ];          // gram partials: 8 K-splits x 16 mats
__device__ float g_inv [8    * MATSZ];          // zero-init; strict-upper blocks stay 0
__device__ float g_T   [8    * MATSZ];
__device__ float g_mean[NMAT * 512];
__device__ float g_msum[NMAT * 512 * 4];
__device__ float g_bias[8    * 512];
__device__ float g_dinv[NMAT * 8 * 64 * 64];    // per-step inv of 64x64 diag blocks

__device__ __nv_bfloat16 g_xhi[NMAT * 512 * 4096];
__device__ __nv_bfloat16 g_xlo[NMAT * 512 * 4096];
__device__ __nv_bfloat16 g_thi[8 * MATSZ];      // zero-init; strict-upper tiles stay 0
__device__ __nv_bfloat16 g_tlo[8 * MATSZ];

// ============================ asm helpers ============================
__device__ __forceinline__ uint32_t smem_to_u32(const void* p) {
    uint32_t a;
    asm("{ .reg .u64 t; cvta.to.shared.u64 t, %1; cvt.u32.u64 %0, t; }" : "=r"(a) : "l"(p));
    return a;
}
__device__ __forceinline__ void ldsm_x4(uint32_t* r, uint32_t addr) {
    asm volatile("ldmatrix.sync.aligned.m8n8.x4.shared.b16 {%0,%1,%2,%3}, [%4];"
        : "=r"(r[0]), "=r"(r[1]), "=r"(r[2]), "=r"(r[3]) : "r"(addr));
}
__device__ __forceinline__ void ldsm_x2(uint32_t* r, uint32_t addr) {
    asm volatile("ldmatrix.sync.aligned.m8n8.x2.shared.b16 {%0,%1}, [%2];"
        : "=r"(r[0]), "=r"(r[1]) : "r"(addr));
}
__device__ __forceinline__ void ldsm_x4_trans(uint32_t* r, uint32_t addr) {
    asm volatile("ldmatrix.sync.aligned.m8n8.x4.trans.shared.b16 {%0,%1,%2,%3}, [%4];"
        : "=r"(r[0]), "=r"(r[1]), "=r"(r[2]), "=r"(r[3]) : "r"(addr));
}
__device__ __forceinline__ void mma16816(float* d, const uint32_t* a, const uint32_t* b) {
    asm volatile("mma.sync.aligned.m16n8k16.row.col.f32.bf16.bf16.f32 "
        "{%0,%1,%2,%3}, {%4,%5,%6,%7}, {%8,%9}, {%0,%1,%2,%3};"
        : "+f"(d[0]), "+f"(d[1]), "+f"(d[2]), "+f"(d[3])
        : "r"(a[0]), "r"(a[1]), "r"(a[2]), "r"(a[3]), "r"(b[0]), "r"(b[1]));
}
#define CP_ASYNC16(sa, gp) \
    asm volatile("cp.async.cg.shared.global [%0], [%1], 16;" :: "r"(sa), "l"(gp))
#define CP_COMMIT() asm volatile("cp.async.commit_group;" ::: "memory")
#define CP_WAIT(n)  asm volatile("cp.async.wait_group %0;" :: "n"(n) : "memory")

// ---------------- 1) fp32 -> bf16 hi/lo split + fused mean partials ----------------
__global__ void convert_x(const float* __restrict__ cont, const float* __restrict__ styl) {
    const size_t i4 = (size_t)blockIdx.x * 256 + threadIdx.x;
    const float4 v = (i4 < 4194304) ? ((const float4*)cont)[i4]
                                    : ((const float4*)styl)[i4 - 4194304];
    float x[4] = {v.x, v.y, v.z, v.w};
    unsigned short hs[4], ls[4];
    #pragma unroll
    for (int j = 0; j < 4; ++j) {
        __nv_bfloat16 h = __float2bfloat16_rn(x[j]);
        __nv_bfloat16 l = __float2bfloat16_rn(x[j] - __bfloat162float(h));
        hs[j] = __bfloat16_as_ushort(h);
        ls[j] = __bfloat16_as_ushort(l);
    }
    ((uint2*)g_xhi)[i4] = make_uint2((uint32_t)hs[0] | ((uint32_t)hs[1] << 16),
                                     (uint32_t)hs[2] | ((uint32_t)hs[3] << 16));
    ((uint2*)g_xlo)[i4] = make_uint2((uint32_t)ls[0] | ((uint32_t)ls[1] << 16),
                                     (uint32_t)ls[2] | ((uint32_t)ls[3] << 16));
    float s = x[0] + x[1] + x[2] + x[3];
    __shared__ float red[256];
    red[threadIdx.x] = s;
    __syncthreads();
    for (int o = 128; o >= 32; o >>= 1) {
        if (threadIdx.x < o) red[threadIdx.x] += red[threadIdx.x + o];
        __syncthreads();
    }
    if (threadIdx.x < 32) {
        float w = red[threadIdx.x];
        #pragma unroll
        for (int o = 16; o; o >>= 1) w += __shfl_xor_sync(0xffffffffu, w, o);
        if (threadIdx.x == 0) g_msum[blockIdx.x] = w;
    }
}

__global__ void finalize_mean() {
    const int idx = blockIdx.x * 256 + threadIdx.x;
    g_mean[idx] = (g_msum[4 * idx] + g_msum[4 * idx + 1] +
                   g_msum[4 * idx + 2] + g_msum[4 * idx + 3]) * (1.f / (float)MPIX);
}

// ---------------- 2) gram GEMM (K-split=8, 3-stage pipeline) ----------------
#define KC       64
#define RSTRIDE  144
#define OPBYTES  (128 * RSTRIDE)
#define RSTRIDEB 272
#define OPBYTESB (64 * RSTRIDEB)
#define STAGEB   (4 * OPBYTES)          // 73728
#define SMEMB    (3 * STAGEB)           // 221184

__global__ void __launch_bounds__(512, 1) gram_gemm() {
    const int p = blockIdx.x;
    int bi = 0;
    while ((bi + 1) * (bi + 2) / 2 <= p) ++bi;
    const int bj = p - bi * (bi + 1) / 2;
    const bool diag = (bi == bj);
    const int mat = blockIdx.z & 15;
    const int split = blockIdx.z >> 4;          // 0..7
    const size_t base = (size_t)mat * 512 * 4096;
    const int K = 4096, NT = 8;
    const int koff = split * 512;
    const __nv_bfloat16* Ah = g_xhi + base + koff + (size_t)(bi * 128) * K;
    const __nv_bfloat16* Al = g_xlo + base + koff + (size_t)(bi * 128) * K;
    const __nv_bfloat16* Bh = g_xhi + base + koff + (size_t)(bj * 128) * K;
    const __nv_bfloat16* Bl = g_xlo + base + koff + (size_t)(bj * 128) * K;

    extern __shared__ __align__(128) char smem[];
    const uint32_t sb = smem_to_u32(smem);
    const int t = threadIdx.x, wid = t >> 5, lane = t & 31;
    const int wm = wid & 3, wn = wid >> 2;
    const int r0 = t >> 3, seg = t & 7;

    float acc[2][4][4];
    #pragma unroll
    for (int a = 0; a < 2; ++a)
        #pragma unroll
        for (int b = 0; b < 4; ++b)
            #pragma unroll
            for (int c = 0; c < 4; ++c) acc[a][b][c] = 0.f;

    const __nv_bfloat16* srcs[4] = {Ah, Al, Bh, Bl};

    auto load_chunk = [&](int c, int stage) {
        const uint32_t s0 = sb + stage * STAGEB;
        #pragma unroll
        for (int op = 0; op < 4; ++op) {
            const __nv_bfloat16* src = srcs[op] + (size_t)c * KC;
            const uint32_t sop = s0 + op * OPBYTES;
            #pragma unroll
            for (int i = 0; i < 2; ++i) {
                const int row = r0 + 64 * i;
                CP_ASYNC16(sop + row * RSTRIDE + seg * 16,
                           src + (size_t)row * K + seg * 8);
            }
        }
    };

    const int l15 = lane & 15;
    const uint32_t a_lane_off = (uint32_t)((wm * 32 + l15) * RSTRIDE + (lane >> 4) * 16);
    const uint32_t b_lane_off = (uint32_t)(2 * OPBYTES +
                                (wn * 32 + (l15 & 7)) * RSTRIDE + ((l15 >> 3) & 1) * 16);

    load_chunk(0, 0); CP_COMMIT();
    load_chunk(1, 1); CP_COMMIT();

    for (int c = 0; c < NT; ++c) {
        const int st = c % 3;
        if (c + 2 < NT) { load_chunk(c + 2, (c + 2) % 3); CP_COMMIT(); CP_WAIT(2); }
        else if (c + 1 < NT) { CP_WAIT(1); }
        else { CP_WAIT(0); }
        __syncthreads();

        const uint32_t base2 = sb + st * STAGEB;
        #pragma unroll
        for (int ks = 0; ks < 4; ++ks) {
            uint32_t ah[2][4], al[2][4], bh[4][2], bl[4][2];
            #pragma unroll
            for (int mt = 0; mt < 2; ++mt) {
                const uint32_t aaddr = base2 + a_lane_off + mt * (16 * RSTRIDE) + ks * 32;
                ldsm_x4(ah[mt], aaddr);
                ldsm_x4(al[mt], aaddr + OPBYTES);
            }
            #pragma unroll
            for (int nt = 0; nt < 4; ++nt) {
                const uint32_t baddr = base2 + b_lane_off + nt * (8 * RSTRIDE) + ks * 32;
                ldsm_x2(bh[nt], baddr);
                ldsm_x2(bl[nt], baddr + OPBYTES);
            }
            #pragma unroll
            for (int mt = 0; mt < 2; ++mt)
                #pragma unroll
                for (int nt = 0; nt < 4; ++nt) {
                    mma16816(acc[mt][nt], ah[mt], bh[nt]);
                    mma16816(acc[mt][nt], ah[mt], bl[nt]);
                    mma16816(acc[mt][nt], al[mt], bh[nt]);
                }
        }
        __syncthreads();
    }

    const int qr = lane >> 2, qc = (lane & 3) * 2;
    float* P = g_part + (size_t)((split << 4) + mat) * MATSZ;
    #pragma unroll
    for (int mt = 0; mt < 2; ++mt)
        #pragma unroll
        for (int v = 0; v < 2; ++v) {
            const int gr = bi * 128 + wm * 32 + mt * 16 + qr + v * 8;
            #pragma unroll
            for (int nt = 0; nt < 4; ++nt)
                #pragma unroll
                for (int j = 0; j < 2; ++j) {
                    const int gc = bj * 128 + wn * 32 + nt * 8 + qc + j;
                    if (!diag || gc <= gr)
                        P[(size_t)gr * 512 + gc] = acc[mt][nt][v * 2 + j];
                }
        }
}

// ---------------- 3) out GEMM: out = T @ xc + bias (trans-B, 3-stage) ----------------
__global__ void __launch_bounds__(512, 1) out_gemm(float* __restrict__ outp) {
    const int bi = blockIdx.x, bj = blockIdx.y, mat = blockIdx.z;
    const int NT = (bi + 1) * 2;
    const __nv_bfloat16* Ah = g_thi + (size_t)mat * MATSZ + (size_t)(bi * 128) * 512;
    const __nv_bfloat16* Al = g_tlo + (size_t)mat * MATSZ + (size_t)(bi * 128) * 512;
    const __nv_bfloat16* Bh = g_xhi + (size_t)mat * 512 * 4096 + bj * 128;
    const __nv_bfloat16* Bl = g_xlo + (size_t)mat * 512 * 4096 + bj * 128;

    extern __shared__ __align__(128) char smem[];
    const uint32_t sb = smem_to_u32(smem);
    const int t = threadIdx.x, wid = t >> 5, lane = t & 31;
    const int wm = wid & 3, wn = wid >> 2;
    const int r0 = t >> 3, seg = t & 7;

    float acc[2][4][4];
    #pragma unroll
    for (int a = 0; a < 2; ++a)
        #pragma unroll
        for (int b = 0; b < 4; ++b)
            #pragma unroll
            for (int c = 0; c < 4; ++c) acc[a][b][c] = 0.f;

    auto load_chunk = [&](int c, int stage) {
        const uint32_t s0 = sb + stage * STAGEB;
        #pragma unroll
        for (int i = 0; i < 2; ++i) {
            const int row = r0 + 64 * i;
            const size_t go = (size_t)row * 512 + (size_t)c * KC + seg * 8;
            CP_ASYNC16(s0 + row * RSTRIDE + seg * 16, Ah + go);
            CP_ASYNC16(s0 + OPBYTES + row * RSTRIDE + seg * 16, Al + go);
        }
        #pragma unroll
        for (int i = 0; i < 2; ++i) {
            const int s = seg + 8 * i;
            const size_t go = (size_t)(c * KC + r0) * 4096 + s * 8;
            CP_ASYNC16(s0 + 2 * OPBYTES + r0 * RSTRIDEB + s * 16, Bh + go);
            CP_ASYNC16(s0 + 2 * OPBYTES + OPBYTESB + r0 * RSTRIDEB + s * 16, Bl + go);
        }
    };

    const int l15 = lane & 15;
    const uint32_t a_lane_off = (uint32_t)((wm * 32 + l15) * RSTRIDE + (lane >> 4) * 16);
    const uint32_t b_lane_off = (uint32_t)(2 * OPBYTES + (lane & 15) * RSTRIDEB +
                                           (wn * 32 + ((lane >> 4) & 1) * 8) * 2);

    load_chunk(0, 0); CP_COMMIT();
    load_chunk(1, 1); CP_COMMIT();

    for (int c = 0; c < NT; ++c) {
        const int st = c % 3;
        if (c + 2 < NT) { load_chunk(c + 2, (c + 2) % 3); CP_COMMIT(); CP_WAIT(2); }
        else if (c + 1 < NT) { CP_WAIT(1); }
        else { CP_WAIT(0); }
        __syncthreads();

        const uint32_t base2 = sb + st * STAGEB;
        #pragma unroll
        for (int ks = 0; ks < 4; ++ks) {
            uint32_t ah[2][4], al[2][4], bh[4][2], bl[4][2];
            #pragma unroll
            for (int mt = 0; mt < 2; ++mt) {
                const uint32_t aaddr = base2 + a_lane_off + mt * (16 * RSTRIDE) + ks * 32;
                ldsm_x4(ah[mt], aaddr);
                ldsm_x4(al[mt], aaddr + OPBYTES);
            }
            #pragma unroll
            for (int ntp = 0; ntp < 2; ++ntp) {
                const uint32_t baddr = base2 + b_lane_off + ks * (16 * RSTRIDEB) + ntp * 32;
                uint32_t r4[4];
                ldsm_x4_trans(r4, baddr);
                bh[2 * ntp][0] = r4[0]; bh[2 * ntp][1] = r4[1];
                bh[2 * ntp + 1][0] = r4[2]; bh[2 * ntp + 1][1] = r4[3];
                ldsm_x4_trans(r4, baddr + OPBYTESB);
                bl[2 * ntp][0] = r4[0]; bl[2 * ntp][1] = r4[1];
                bl[2 * ntp + 1][0] = r4[2]; bl[2 * ntp + 1][1] = r4[3];
            }
            #pragma unroll
            for (int mt = 0; mt < 2; ++mt)
                #pragma unroll
                for (int nt = 0; nt < 4; ++nt) {
                    mma16816(acc[mt][nt], ah[mt], bh[nt]);
                    mma16816(acc[mt][nt], ah[mt], bl[nt]);
                    mma16816(acc[mt][nt], al[mt], bh[nt]);
                }
        }
        __syncthreads();
    }

    const int qr = lane >> 2, qc = (lane & 3) * 2;
    #pragma unroll
    for (int mt = 0; mt < 2; ++mt)
        #pragma unroll
        for (int v = 0; v < 2; ++v) {
            const int gm = bi * 128 + wm * 32 + mt * 16 + qr + v * 8;
            const float bv = g_bias[mat * 512 + gm];
            float* orow = outp + ((size_t)mat * 512 + gm) * 4096 + bj * 128 + wn * 32;
            #pragma unroll
            for (int nt = 0; nt < 4; ++nt) {
                float2 pr;
                pr.x = acc[mt][nt][v * 2 + 0] + bv;
                pr.y = acc[mt][nt][v * 2 + 1] + bv;
                *(float2*)&orow[nt * 8 + qc] = pr;
            }
        }
}

// combine 8 partials; mirror = 0 (upper never read downstream)
__global__ void combine_cov() {
    const int mat = blockIdx.y, i = blockIdx.x;
    const float* mrow = g_mean + mat * 512;
    float* C = g_cov + (size_t)mat * MATSZ;
    const float mi = mrow[i] * (float)MPIX;
    const float invm1 = 1.f / (float)(MPIX - 1);
    for (int j = threadIdx.x; j <= i; j += 256) {
        const size_t o = (size_t)i * 512 + j;
        float s = 0.f;
        #pragma unroll
        for (int sp = 0; sp < 8; ++sp)
            s += g_part[(size_t)((sp << 4) + mat) * MATSZ + o];
        C[o] = (s - mi * mrow[j]) * invm1;
        if (j < i) C[(size_t)j * 512 + i] = 0.f;
    }
}

// ---------------- 4) blocked Cholesky (bs=64), 256 threads, micro-blocked ----------
__global__ void __launch_bounds__(256) chol_diag(int s) {
    const int mat = blockIdx.x;
    float* A = g_cov + (size_t)mat * MATSZ;
    __shared__ float sA[64][65];
    __shared__ float sW[64][65];
    const int t = threadIdx.x;
    for (int idx = t; idx < 4096; idx += 256) {
        int r = idx >> 6, c = idx & 63;
        sA[r][c] = A[(size_t)(s * 64 + r) * 512 + s * 64 + c];
        sW[r][c] = 0.f;
    }
    __syncthreads();

    for (int sbk = 0; sbk < 8; ++sbk) {
        const int o = sbk * 8;
        if (t < 8) {
            const int r = t;
            for (int j = 0; j < 8; ++j) {
                if (r == j) sA[o + j][o + j] = sqrtf(sA[o + j][o + j]);
                __syncwarp(0xFFu);
                const float d = sA[o + j][o + j];
                if (r > j) sA[o + r][o + j] /= d;
                __syncwarp(0xFFu);
                if (r > j) {
                    const float lrj = sA[o + r][o + j];
                    for (int c = j + 1; c <= r; ++c) sA[o + r][o + c] -= lrj * sA[o + c][o + j];
                }
                __syncwarp(0xFFu);
            }
        }
        __syncthreads();
        const int nrem = 64 - o - 8;
        if (nrem > 0) {
            if (t < nrem) {
                const int r = o + 8 + t;
                float x[8];
                #pragma unroll
                for (int j = 0; j < 8; ++j) {
                    float v = sA[r][o + j];
                    #pragma unroll
                    for (int k = 0; k < 8; ++k)
                        if (k < j) v -= x[k] * sA[o + j][o + k];
                    x[j] = v / sA[o + j][o + j];
                }
                #pragma unroll
                for (int j = 0; j < 8; ++j) sA[r][o + j] = x[j];
            }
            __syncthreads();
            const int tot = nrem * nrem;
            for (int e = t; e < tot; e += 256) {
                const int r = o + 8 + e / nrem, c = o + 8 + e % nrem;
                float v = sA[r][c];
                #pragma unroll
                for (int k = 0; k < 8; ++k) v -= sA[r][o + k] * sA[c][o + k];
                sA[r][c] = v;
            }
            __syncthreads();
        }
    }

    {
        const int col = t >> 2, part = t & 3;
        const uint32_t qmask = 0xFu << ((t & 31) & ~3u);
        if (part == 0) sW[col][col] = 1.f / sA[col][col];
        __syncwarp(qmask);
        for (int i = col + 1; i < 64; ++i) {
            float psum = 0.f;
            for (int k = col + part; k < i; k += 4) psum += sA[i][k] * sW[k][col];
            psum += __shfl_down_sync(qmask, psum, 1);
            psum += __shfl_down_sync(qmask, psum, 2);
            if (part == 0) sW[i][col] = -psum / sA[i][i];
            __syncwarp(qmask);
        }
    }
    __syncthreads();

    float* D = g_dinv + (size_t)(mat * 8 + s) * 4096;
    float* W = (mat < 8) ? (g_inv + (size_t)mat * MATSZ) : nullptr;
    for (int idx = t; idx < 4096; idx += 256) {
        int r = idx >> 6, c = idx & 63;
        if (c <= r) A[(size_t)(s * 64 + r) * 512 + s * 64 + c] = sA[r][c];
        D[idx] = sW[r][c];
        if (W) W[(size_t)(s * 64 + r) * 512 + s * 64 + c] = sW[r][c];
    }
}

// TRSM as GEMM: panel = A21 * invL11^T
__global__ void __launch_bounds__(256) trsm_gemm(int s) {
    const int mat = blockIdx.y;
    float* A = g_cov + (size_t)mat * MATSZ;
    const float* D = g_dinv + (size_t)(mat * 8 + s) * 4096;
    const int g0 = (s + 1) * 64 + blockIdx.x * 64;
    __shared__ float sa[64][68];
    __shared__ float sw[64][68];
    const int t = threadIdx.x;
    {
        const int row = t >> 2, kq = t & 3;
        #pragma unroll
        for (int i2 = 0; i2 < 4; ++i2) {
            const int k = kq * 16 + i2 * 4;
            float4 va = *(const float4*)&A[(size_t)(g0 + row) * 512 + s * 64 + k];
            sa[k + 0][row] = va.x; sa[k + 1][row] = va.y; sa[k + 2][row] = va.z; sa[k + 3][row] = va.w;
            float4 vw = *(const float4*)&D[row * 64 + k];
            sw[k + 0][row] = vw.x; sw[k + 1][row] = vw.y; sw[k + 2][row] = vw.z; sw[k + 3][row] = vw.w;
        }
    }
    __syncthreads();
    const int i0 = (t >> 4) << 2, j0 = (t & 15) << 2;
    float acc[4][4];
    #pragma unroll
    for (int i = 0; i < 4; ++i)
        #pragma unroll
        for (int j = 0; j < 4; ++j) acc[i][j] = 0.f;
    #pragma unroll 8
    for (int k = 0; k < 64; ++k) {
        float4 a = *(const float4*)&sa[k][i0];
        float4 b = *(const float4*)&sw[k][j0];
        float av[4] = {a.x, a.y, a.z, a.w}, bv[4] = {b.x, b.y, b.z, b.w};
        #pragma unroll
        for (int i = 0; i < 4; ++i)
            #pragma unroll
            for (int j = 0; j < 4; ++j) acc[i][j] += av[i] * bv[j];
    }
    #pragma unroll
    for (int i = 0; i < 4; ++i)
        #pragma unroll
        for (int j = 0; j < 4; ++j)
            A[(size_t)(g0 + i0 + i) * 512 + s * 64 + j0 + j] = acc[i][j];
}

// SYRK with tile offset: ti = bx+off, tj = by+off (off=0 grid(n,1): column 0;
// off=1 grid(n-1,n-1): remaining tiles)
__global__ void __launch_bounds__(256) syrk_update(int s, int off) {
    const int ti = blockIdx.x + off, tj = blockIdx.y + off, mat = blockIdx.z;
    if (ti < tj) return;
    float* A = g_cov + (size_t)mat * MATSZ;
    const int base = (s + 1) * 64;
    const int R0 = base + ti * 64, C0 = base + tj * 64;
    __shared__ float sa[64][68];
    __shared__ float sb2[64][68];
    const int t = threadIdx.x;
    {
        const int row = t >> 2, kq = t & 3;
        #pragma unroll
        for (int i2 = 0; i2 < 4; ++i2) {
            const int k = kq * 16 + i2 * 4;
            float4 va = *(const float4*)&A[(size_t)(R0 + row) * 512 + s * 64 + k];
            sa[k + 0][row] = va.x; sa[k + 1][row] = va.y; sa[k + 2][row] = va.z; sa[k + 3][row] = va.w;
            float4 vb = *(const float4*)&A[(size_t)(C0 + row) * 512 + s * 64 + k];
            sb2[k + 0][row] = vb.x; sb2[k + 1][row] = vb.y; sb2[k + 2][row] = vb.z; sb2[k + 3][row] = vb.w;
        }
    }
    __syncthreads();
    const int i0 = (t >> 4) << 2, j0 = (t & 15) << 2;
    float acc[4][4];
    #pragma unroll
    for (int i = 0; i < 4; ++i)
        #pragma unroll
        for (int j = 0; j < 4; ++j) acc[i][j] = 0.f;
    #pragma unroll 8
    for (int k = 0; k < 64; ++k) {
        float4 a = *(const float4*)&sa[k][i0];
        float4 b = *(const float4*)&sb2[k][j0];
        float av[4] = {a.x, a.y, a.z, a.w}, bv[4] = {b.x, b.y, b.z, b.w};
        #pragma unroll
        for (int i = 0; i < 4; ++i)
            #pragma unroll
            for (int j = 0; j < 4; ++j) acc[i][j] += av[i] * bv[j];
    }
    #pragma unroll
    for (int i = 0; i < 4; ++i) {
        const int li = i0 + i;
        #pragma unroll
        for (int j = 0; j < 4; ++j) {
            const int lj = j0 + j;
            if (ti != tj || li >= lj)
                A[(size_t)(R0 + li) * 512 + C0 + lj] -= acc[i][j];
        }
    }
}

// ---------------- 5) blocked inv(Lc): fused column-sweep ----------------
#define SWELEM 4160
#define TRINV_SMEM ((8 * SWELEM + 2 * 64 * 68) * 4)

__global__ void __launch_bounds__(256) trinv_cols() {
    const int jb = blockIdx.x % 7, mat = blockIdx.x / 7;
    const float* L = g_cov + (size_t)mat * MATSZ;
    float* W = g_inv + (size_t)mat * MATSZ;

    extern __shared__ float sm[];
    float* sW = sm;
    float* sa = sm + 8 * SWELEM;
    float* sb = sa + 64 * 68;
    #define SWB(b, r, c) sW[(b) * SWELEM + (r) * 65 + (c)]
    #define SAB(r, c)    sa[(r) * 68 + (c)]
    #define SBB(r, c)    sb[(r) * 68 + (c)]

    const int t = threadIdx.x;
    const int i0 = (t >> 4) << 2, j0 = (t & 15) << 2;

    for (int idx = t; idx < 4096; idx += 256) {
        int r = idx >> 6, c = idx & 63;
        SWB(0, r, c) = W[(size_t)(jb * 64 + r) * 512 + jb * 64 + c];
    }
    __syncthreads();

    for (int ib = jb + 1; ib < 8; ++ib) {
        float acc[4][4];
        #pragma unroll
        for (int i = 0; i < 4; ++i)
            #pragma unroll
            for (int j = 0; j < 4; ++j) acc[i][j] = 0.f;

        for (int k = jb; k < ib; ++k) {
            __syncthreads();
            {
                const int row = t >> 2, kq = t & 3;
                #pragma unroll
                for (int i2 = 0; i2 < 4; ++i2) {
                    const int kk = kq * 16 + i2 * 4;
                    float4 va = *(const float4*)&L[(size_t)(ib * 64 + row) * 512 + k * 64 + kk];
                    SAB(kk + 0, row) = va.x; SAB(kk + 1, row) = va.y;
                    SAB(kk + 2, row) = va.z; SAB(kk + 3, row) = va.w;
                }
            }
            __syncthreads();
            const int kb = k - jb;
            #pragma unroll 8
            for (int kk = 0; kk < 64; ++kk) {
                float av[4], bv[4];
                #pragma unroll
                for (int i = 0; i < 4; ++i) av[i] = SAB(kk, i0 + i);
                #pragma unroll
                for (int j = 0; j < 4; ++j) bv[j] = SWB(kb, kk, j0 + j);
                #pragma unroll
                for (int i = 0; i < 4; ++i)
                    #pragma unroll
                    for (int j = 0; j < 4; ++j) acc[i][j] += av[i] * bv[j];
            }
        }
        __syncthreads();
        #pragma unroll
        for (int i = 0; i < 4; ++i)
            #pragma unroll
            for (int j = 0; j < 4; ++j) SBB(i0 + i, j0 + j) = acc[i][j];
        {
            const int row = t >> 2, kq = t & 3;
            #pragma unroll
            for (int i2 = 0; i2 < 4; ++i2) {
                const int kk = kq * 16 + i2 * 4;
                float4 va = *(const float4*)&W[(size_t)(ib * 64 + row) * 512 + ib * 64 + kk];
                SAB(kk + 0, row) = va.x; SAB(kk + 1, row) = va.y;
                SAB(kk + 2, row) = va.z; SAB(kk + 3, row) = va.w;
            }
        }
        __syncthreads();
        float acc2[4][4];
        #pragma unroll
        for (int i = 0; i < 4; ++i)
            #pragma unroll
            for (int j = 0; j < 4; ++j) acc2[i][j] = 0.f;
        #pragma unroll 8
        for (int kk = 0; kk < 64; ++kk) {
            float av[4], bv[4];
            #pragma unroll
            for (int i = 0; i < 4; ++i) av[i] = SAB(kk, i0 + i);
            #pragma unroll
            for (int j = 0; j < 4; ++j) bv[j] = SBB(kk, j0 + j);
            #pragma unroll
            for (int i = 0; i < 4; ++i)
                #pragma unroll
                for (int j = 0; j < 4; ++j) acc2[i][j] += av[i] * bv[j];
        }
        const int kb = ib - jb;
        #pragma unroll
        for (int i = 0; i < 4; ++i)
            #pragma unroll
            for (int j = 0; j < 4; ++j) {
                const float v = -acc2[i][j];
                SWB(kb, i0 + i, j0 + j) = v;
                W[(size_t)(ib * 64 + i0 + i) * 512 + jb * 64 + j0 + j] = v;
            }
    }
}

// ---------------- 6) triangular T = Ls @ W; fused bf16 split epilogue ----------------
__global__ void __launch_bounds__(256) gemm_nn_tri() {
    const int p = blockIdx.x, mat = blockIdx.y;
    int bm = 0;
    while ((bm + 1) * (bm + 2) / 2 <= p) ++bm;
    const int bn = p - bm * (bm + 1) / 2;
    const float* A = g_cov + (size_t)(8 + mat) * MATSZ;
    const float* B = g_inv + (size_t)mat * MATSZ;
    float* C = g_T + (size_t)mat * MATSZ;

    __shared__ float As[2][16][TPAD];
    __shared__ float Bs[2][16][128];

    const int t = threadIdx.x;
    const int arow = t & 127, akg = t >> 7;
    const int kt0 = bn * 8;
    const int NT = (bm + 1) * 8 - kt0;
    const float* aptr = A + (size_t)(bm * 128 + arow) * 512 + kt0 * 16 + akg * 8;
    const int bkr = t >> 5, bc = (t & 31) << 2;
    const float* bptr = B + (size_t)(kt0 * 16 + bkr) * 512 + bn * 128 + bc;
    const int m0 = (t >> 4) << 3, n0 = (t & 15) << 3;

    float acc[8][8];
    #pragma unroll
    for (int i = 0; i < 8; ++i)
        #pragma unroll
        for (int j = 0; j < 8; ++j) acc[i][j] = 0.f;

    {
        float av[8];
        *(float4*)&av[0] = *(const float4*)(aptr);
        *(float4*)&av[4] = *(const float4*)(aptr + 4);
        const int kb = akg * 8;
        #pragma unroll
        for (int c = 0; c < 8; ++c) As[0][kb + c][arow] = av[c];
        float4 v0 = *(const float4*)(bptr);
        float4 v1 = *(const float4*)(bptr + (size_t)8 * 512);
        *(float4*)&Bs[0][bkr][bc]     = v0;
        *(float4*)&Bs[0][bkr + 8][bc] = v1;
    }
    __syncthreads();

    for (int kt = 0; kt < NT; ++kt) {
        const int cur = kt & 1;
        if (kt + 1 < NT) {
            const int nb = cur ^ 1;
            float av[8];
            const float* ap = aptr + (kt + 1) * 16;
            *(float4*)&av[0] = *(const float4*)(ap);
            *(float4*)&av[4] = *(const float4*)(ap + 4);
            const int kb = akg * 8;
            #pragma unroll
            for (int c = 0; c < 8; ++c) As[nb][kb + c][arow] = av[c];
            const float* bp = bptr + (size_t)((kt + 1) * 16) * 512;
            float4 v0 = *(const float4*)(bp);
            float4 v1 = *(const float4*)(bp + (size_t)8 * 512);
            *(float4*)&Bs[nb][bkr][bc]     = v0;
            *(float4*)&Bs[nb][bkr + 8][bc] = v1;
        }
        #pragma unroll
        for (int k = 0; k < 16; ++k) {
            float a[8], b[8];
            *(float4*)&a[0] = *(const float4*)&As[cur][k][m0];
            *(float4*)&a[4] = *(const float4*)&As[cur][k][m0 + 4];
            *(float4*)&b[0] = *(const float4*)&Bs[cur][k][n0];
            *(float4*)&b[4] = *(const float4*)&Bs[cur][k][n0 + 4];
            #pragma unroll
            for (int i = 0; i < 8; ++i)
                #pragma unroll
                for (int j = 0; j < 8; ++j) acc[i][j] += a[i] * b[j];
        }
        __syncthreads();
    }

    const bool dtile = (bm == bn);
    __nv_bfloat16* TH = g_thi + (size_t)mat * MATSZ;
    __nv_bfloat16* TL = g_tlo + (size_t)mat * MATSZ;
    #pragma unroll
    for (int i = 0; i < 8; ++i) {
        const int gi = bm * 128 + m0 + i;
        #pragma unroll
        for (int j = 0; j < 8; ++j) {
            const int gj = bn * 128 + n0 + j;
            const float v = acc[i][j];
            C[(size_t)gi * 512 + gj] = v;
            const float vm = (dtile && gj > gi) ? 0.f : v;
            __nv_bfloat16 h = __float2bfloat16_rn(vm);
            __nv_bfloat16 l = __float2bfloat16_rn(vm - __bfloat162float(h));
            TH[(size_t)gi * 512 + gj] = h;
            TL[(size_t)gi * 512 + gj] = l;
        }
    }
}

// ---------------- 7) bias = ms - T @ mc ----------------
__global__ void bias_kernel() {
    const int w = threadIdx.x >> 5, lane = threadIdx.x & 31;
    const int g = blockIdx.x * 8 + w;
    const int b = g >> 9, i = g & 511;
    const float* Trow = g_T + (size_t)b * MATSZ + (size_t)i * 512;
    const float* mc = g_mean + b * 512;
    float acc = 0.f;
    for (int k = lane; k <= i; k += 32) acc += Trow[k] * mc[k];
    #pragma unroll
    for (int o = 16; o; o >>= 1) acc += __shfl_xor_sync(0xffffffffu, acc, o);
    if (lane == 0) g_bias[g] = g_mean[(8 + b) * 512 + i] - acc;
}

// ---------------- launcher ----------------
extern "C" void kernel_launch(void* const* d_in, const int* in_sizes, int n_in,
                              void* d_out, int out_size) {
    const float* cont = (const float*)d_in[0];
    const float* styl = (const float*)d_in[1];
    float* out = (float*)d_out;

    static cudaStream_t s2 = nullptr;
    static cudaEvent_t evT[8], evR[8];
    if (!s2) {
        cudaStreamCreateWithFlags(&s2, cudaStreamNonBlocking);
        for (int i = 0; i < 8; ++i) {
            cudaEventCreateWithFlags(&evT[i], cudaEventDisableTiming);
            cudaEventCreateWithFlags(&evR[i], cudaEventDisableTiming);
        }
    }

    cudaFuncSetAttribute(gram_gemm, cudaFuncAttributeMaxDynamicSharedMemorySize, SMEMB);
    cudaFuncSetAttribute(out_gemm,  cudaFuncAttributeMaxDynamicSharedMemorySize, SMEMB);
    cudaFuncSetAttribute(trinv_cols, cudaFuncAttributeMaxDynamicSharedMemorySize, TRINV_SMEM);

    convert_x<<<32768, 256>>>(cont, styl);
    finalize_mean<<<32, 256>>>();

    gram_gemm<<<dim3(10, 1, 128), 512, SMEMB>>>();
    combine_cov<<<dim3(512, 16), 256>>>();

    int lastR = -1;
    for (int s = 0; s < 8; ++s) {
        chol_diag<<<NMAT, 256>>>(s);
        const int n = (512 - (s + 1) * 64) / 64;
        if (n > 0) {
            trsm_gemm<<<dim3(n, NMAT), 256>>>(s);
            if (n > 1) {
                cudaEventRecord(evT[s], 0);
                cudaStreamWaitEvent(s2, evT[s], 0);
                syrk_update<<<dim3(n - 1, n - 1, NMAT), 256, 0, s2>>>(s, 1);
                cudaEventRecord(evR[s], s2);
            }
            if (lastR >= 0) cudaStreamWaitEvent(0, evR[lastR], 0);
            syrk_update<<<dim3(n, 1, NMAT), 256>>>(s, 0);   // column-0 tiles on critical path
            if (n > 1) lastR = s;
        }
    }
    if (lastR >= 0) cudaStreamWaitEvent(0, evR[lastR], 0);

    trinv_cols<<<56, 256, TRINV_SMEM>>>();

    gemm_nn_tri<<<dim3(10, 8), 256>>>();

    bias_kernel<<<512, 256>>>();
    out_gemm<<<dim3(4, 32, 8), 512, SMEMB>>>(out);
}